// round 5
// baseline (speedup 1.0000x reference)
#include <cuda_runtime.h>
#include <cstdint>

#define HIDDEN   256
#define NHL      4
#define MTILE    64
#define KS       16
#define NSLAB    16         // HIDDEN / KS
#define THREADS  256
#define NSLABS_TOTAL (NHL * NSLAB)
#define SLAB_BYTES (KS * HIDDEN * 4)

// smem (floats): xa[64*256] wbuf[2*16*256] omg[64] cs[256] wfs[256] mbar[4]
#define SMEM_FLOATS (MTILE*HIDDEN + 2*KS*HIDDEN + MTILE + MTILE*4 + HIDDEN + 8)

// ---- packed fp32x2 helpers (FFMA2 path) ----
__device__ __forceinline__ void fma2(uint64_t& d, uint64_t a, uint64_t b) {
    asm volatile("fma.rn.f32x2 %0, %1, %2, %0;" : "+l"(d) : "l"(a), "l"(b));
}
__device__ __forceinline__ uint64_t fma2v(uint64_t a, uint64_t b, uint64_t c) {
    uint64_t d; asm("fma.rn.f32x2 %0, %1, %2, %3;" : "=l"(d) : "l"(a), "l"(b), "l"(c)); return d;
}
__device__ __forceinline__ uint64_t mul2(uint64_t a, uint64_t b) {
    uint64_t d; asm("mul.rn.f32x2 %0, %1, %2;" : "=l"(d) : "l"(a), "l"(b)); return d;
}
__device__ __forceinline__ uint64_t add2(uint64_t a, uint64_t b) {
    uint64_t d; asm("add.rn.f32x2 %0, %1, %2;" : "=l"(d) : "l"(a), "l"(b)); return d;
}
__device__ __forceinline__ uint64_t dup2(float x) {
    uint64_t d; asm("mov.b64 %0, {%1, %1};" : "=l"(d) : "f"(x)); return d;
}
__device__ __forceinline__ uint64_t pack2(float lo, float hi) {
    uint64_t d; asm("mov.b64 %0, {%1, %2};" : "=l"(d) : "f"(lo), "f"(hi)); return d;
}
__device__ __forceinline__ uint64_t c2(float x) {
    uint64_t d; asm("mov.b64 %0, {%1, %1};" : "=l"(d) : "f"(x)); return d;
}

// packed sine: magic-number range reduction to [-pi,pi] + degree-15 odd poly; no MUFU
__device__ __forceinline__ uint64_t sin2(uint64_t x) {
    uint64_t n = add2(fma2v(x, c2(0.15915494309189535f), c2(12582912.0f)),
                      c2(-12582912.0f));
    uint64_t r = fma2v(n, c2(-6.2831854820251465f), x);
    r = fma2v(n, c2(1.7484555e-7f), r);
    uint64_t r2 = mul2(r, r);
    uint64_t p = c2(-7.6471637e-13f);
    p = fma2v(p, r2, c2(1.6059044e-10f));
    p = fma2v(p, r2, c2(-2.5052108e-8f));
    p = fma2v(p, r2, c2(2.7557319e-6f));
    p = fma2v(p, r2, c2(-1.9841270e-4f));
    p = fma2v(p, r2, c2(8.3333333e-3f));
    p = fma2v(p, r2, c2(-1.6666667e-1f));
    p = fma2v(p, r2, c2(1.0f));
    return mul2(p, r);
}

__device__ __forceinline__ float4 ldg4(const float* p) {
    return __ldg(reinterpret_cast<const float4*>(p));
}

// ---- mbarrier + bulk-copy helpers ----
__device__ __forceinline__ void mbar_init(uint32_t mbar, uint32_t count) {
    asm volatile("mbarrier.init.shared.b64 [%0], %1;" :: "r"(mbar), "r"(count) : "memory");
}
__device__ __forceinline__ void mbar_expect_tx(uint32_t mbar, uint32_t bytes) {
    asm volatile("mbarrier.arrive.expect_tx.shared.b64 _, [%0], %1;"
                 :: "r"(mbar), "r"(bytes) : "memory");
}
__device__ __forceinline__ void mbar_wait(uint32_t mbar, uint32_t parity) {
    uint32_t done;
    asm volatile(
        "{\n\t.reg .pred p;\n\t"
        "mbarrier.try_wait.parity.acquire.cta.shared::cta.b64 p, [%1], %2;\n\t"
        "selp.b32 %0, 1, 0, p;\n\t}"
        : "=r"(done) : "r"(mbar), "r"(parity) : "memory");
    if (!done) {
        asm volatile(
            "{\n\t.reg .pred P1;\n\t"
            "WL_%=:\n\t"
            "mbarrier.try_wait.parity.acquire.cta.shared::cta.b64 P1, [%0], %1, 0x989680;\n\t"
            "@P1 bra.uni WD_%=;\n\t"
            "bra.uni WL_%=;\n\t"
            "WD_%=:\n\t}"
            :: "r"(mbar), "r"(parity) : "memory");
    }
}
__device__ __forceinline__ void bulk_copy(uint32_t smem_dst, const void* gsrc,
                                          uint32_t bytes, uint32_t mbar) {
    asm volatile(
        "cp.async.bulk.shared::cta.global.mbarrier::complete_tx::bytes [%0], [%1], %2, [%3];"
        :: "r"(smem_dst), "l"(gsrc), "r"(bytes), "r"(mbar) : "memory");
}
__device__ __forceinline__ void fence_proxy_async_cta() {
    asm volatile("fence.proxy.async.shared::cta;" ::: "memory");
}

__global__ void __launch_bounds__(THREADS, 2)
siren_fused_kernel(const float* __restrict__ coords,
                   const float* __restrict__ ow1, const float* __restrict__ ob1,
                   const float* __restrict__ ow2, const float* __restrict__ ob2,
                   const float* __restrict__ w0,  const float* __restrict__ b0,
                   const float* __restrict__ wh,  const float* __restrict__ bh,
                   const float* __restrict__ wf,  const float* __restrict__ bf,
                   float* __restrict__ out)
{
    extern __shared__ __align__(16) float smem[];
    float* xa   = smem;                       // [64][256] per-warp rows, in-place
    float* wbuf = xa + MTILE * HIDDEN;        // [2][KS*HIDDEN]
    float* omg  = wbuf + 2 * KS * HIDDEN;     // [64]
    float* cs   = omg + MTILE;                // [64][4]
    float* wfs  = cs + MTILE * 4;             // [256]
    float* mbf  = wfs + HIDDEN;               // 2 x 8B mbarriers

    const int tid = threadIdx.x;
    const int mt  = tid >> 5;
    const int nt  = tid & 31;
    const int m0  = mt * 8;
    const int cA  = nt * 4;
    const int cB  = 128 + nt * 4;
    const long base = (long)blockIdx.x * MTILE;

    const uint32_t mbar0 = (uint32_t)__cvta_generic_to_shared(mbf);
    const uint32_t mbar1 = mbar0 + 8;
    const uint32_t wbuf0 = (uint32_t)__cvta_generic_to_shared(wbuf);

    if (tid == 0) {
        mbar_init(mbar0, 1);
        mbar_init(mbar1, 1);
        fence_proxy_async_cta();
    }
    __syncthreads();

    // prefetch slab 0 with a single bulk DMA (no per-thread LDGSTS)
    if (tid == 0) {
        mbar_expect_tx(mbar0, SLAB_BYTES);
        bulk_copy(wbuf0, wh, SLAB_BYTES, mbar0);
    }

    cs[tid]  = coords[base * 4 + tid];
    wfs[tid] = wf[tid];
    __syncthreads();

    // ---- omega predictor (threads 0..63) ----
    if (tid < MTILE) {
        float c0 = cs[tid * 4 + 0], c1 = cs[tid * 4 + 1];
        float c2v = cs[tid * 4 + 2], c3 = cs[tid * 4 + 3];
        float s = __ldg(ob2);
        #pragma unroll 4
        for (int j = 0; j < 64; j++) {
            float h = __ldg(&ow1[j]) * c0;
            h = fmaf(__ldg(&ow1[64  + j]), c1, h);
            h = fmaf(__ldg(&ow1[128 + j]), c2v, h);
            h = fmaf(__ldg(&ow1[192 + j]), c3, h);
            h += __ldg(&ob1[j]);
            h = fmaxf(h, 0.0f);
            s = fmaf(h, __ldg(&ow2[j]), s);
        }
        float sig = 1.0f / (1.0f + __expf(-s));
        omg[tid] = 10.0f + 90.0f * sig;
    }
    __syncthreads();

    // ---- SIREN layer 0: x = sin(omega * (coords @ w0 + b0)), K=4 ----
    {
        float accA[8][4], accB[8][4];
        #pragma unroll
        for (int i = 0; i < 8; i++)
            #pragma unroll
            for (int j = 0; j < 4; j++) { accA[i][j] = 0.0f; accB[i][j] = 0.0f; }
        #pragma unroll
        for (int k = 0; k < 4; k++) {
            float4 bA = ldg4(&w0[k * HIDDEN + cA]);
            float4 bB = ldg4(&w0[k * HIDDEN + cB]);
            #pragma unroll
            for (int i = 0; i < 8; i++) {
                float a = cs[(m0 + i) * 4 + k];
                accA[i][0] = fmaf(a, bA.x, accA[i][0]);
                accA[i][1] = fmaf(a, bA.y, accA[i][1]);
                accA[i][2] = fmaf(a, bA.z, accA[i][2]);
                accA[i][3] = fmaf(a, bA.w, accA[i][3]);
                accB[i][0] = fmaf(a, bB.x, accB[i][0]);
                accB[i][1] = fmaf(a, bB.y, accB[i][1]);
                accB[i][2] = fmaf(a, bB.z, accB[i][2]);
                accB[i][3] = fmaf(a, bB.w, accB[i][3]);
            }
        }
        ulonglong2 biA = __ldg(reinterpret_cast<const ulonglong2*>(&b0[cA]));
        ulonglong2 biB = __ldg(reinterpret_cast<const ulonglong2*>(&b0[cB]));
        #pragma unroll
        for (int i = 0; i < 8; i++) {
            uint64_t om2 = dup2(omg[m0 + i]);
            ulonglong2 vA, vB;
            vA.x = sin2(mul2(om2, add2(pack2(accA[i][0], accA[i][1]), biA.x)));
            vA.y = sin2(mul2(om2, add2(pack2(accA[i][2], accA[i][3]), biA.y)));
            vB.x = sin2(mul2(om2, add2(pack2(accB[i][0], accB[i][1]), biB.x)));
            vB.y = sin2(mul2(om2, add2(pack2(accB[i][2], accB[i][3]), biB.y)));
            *reinterpret_cast<ulonglong2*>(&xa[(m0 + i) * HIDDEN + cA]) = vA;
            *reinterpret_cast<ulonglong2*>(&xa[(m0 + i) * HIDDEN + cB]) = vB;
        }
    }
    __syncwarp();

    // ---- 4 hidden layers, in-place xa, FFMA2 mainloop, bulk-DMA weight stream ----
    #pragma unroll 1
    for (int l = 0; l < NHL; l++) {
        uint64_t accA[8][2], accB[8][2];
        #pragma unroll
        for (int i = 0; i < 8; i++) {
            accA[i][0] = 0ull; accA[i][1] = 0ull;
            accB[i][0] = 0ull; accB[i][1] = 0ull;
        }

        #pragma unroll 1
        for (int s = 0; s < NSLAB; s++) {
            int g = l * NSLAB + s;
            // prefetch slab g+1 into buffer (g+1)&1 — freed by the __syncthreads
            // at the end of slab g-1, which precedes this point.
            if (tid == 0 && g + 1 < NSLABS_TOTAL) {
                uint32_t mb = ((g + 1) & 1) ? mbar1 : mbar0;
                mbar_expect_tx(mb, SLAB_BYTES);
                bulk_copy(wbuf0 + ((g + 1) & 1) * SLAB_BYTES,
                          wh + (size_t)(g + 1) * KS * HIDDEN, SLAB_BYTES, mb);
            }
            // wait for slab g data (acquire)
            mbar_wait((g & 1) ? mbar1 : mbar0, (g >> 1) & 1);

            const float* wb = wbuf + (g & 1) * (KS * HIDDEN);
            const float* xk = &xa[m0 * HIDDEN + s * KS];

            #pragma unroll 2
            for (int kp = 0; kp < KS / 2; kp++) {
                float2 a[8];
                #pragma unroll
                for (int i = 0; i < 8; i++)
                    a[i] = *reinterpret_cast<const float2*>(xk + i * HIDDEN + kp * 2);
                #pragma unroll
                for (int kk = 0; kk < 2; kk++) {
                    ulonglong2 bA = *reinterpret_cast<const ulonglong2*>(&wb[(kp * 2 + kk) * HIDDEN + cA]);
                    ulonglong2 bB = *reinterpret_cast<const ulonglong2*>(&wb[(kp * 2 + kk) * HIDDEN + cB]);
                    #pragma unroll
                    for (int i = 0; i < 8; i++) {
                        uint64_t ad = dup2(kk ? a[i].y : a[i].x);
                        fma2(accA[i][0], ad, bA.x);
                        fma2(accA[i][1], ad, bA.y);
                        fma2(accB[i][0], ad, bB.x);
                        fma2(accB[i][1], ad, bB.y);
                    }
                }
            }
            __syncthreads();   // all warps done with buffer g&1 before it is refilled
        }

        ulonglong2 bhA = __ldg(reinterpret_cast<const ulonglong2*>(&bh[l * HIDDEN + cA]));
        ulonglong2 bhB = __ldg(reinterpret_cast<const ulonglong2*>(&bh[l * HIDDEN + cB]));
        __syncwarp();
        #pragma unroll
        for (int i = 0; i < 8; i++) {
            uint64_t om2 = dup2(omg[m0 + i]);
            ulonglong2 vA, vB;
            vA.x = sin2(mul2(om2, add2(accA[i][0], bhA.x)));
            vA.y = sin2(mul2(om2, add2(accA[i][1], bhA.y)));
            vB.x = sin2(mul2(om2, add2(accB[i][0], bhB.x)));
            vB.y = sin2(mul2(om2, add2(accB[i][1], bhB.y)));
            *reinterpret_cast<ulonglong2*>(&xa[(m0 + i) * HIDDEN + cA]) = vA;
            *reinterpret_cast<ulonglong2*>(&xa[(m0 + i) * HIDDEN + cB]) = vB;
        }
        __syncwarp();
    }

    // ---- head: out[m] = x[m] @ wf + bf ----
    {
        const int w = tid >> 5, lane = tid & 31;
        const float bfv = __ldg(bf);
        const float4* wr = reinterpret_cast<const float4*>(&wfs[lane * 8]);
        float4 w1 = wr[0], w2 = wr[1];
        #pragma unroll
        for (int p = 0; p < 8; p++) {
            int m = w * 8 + p;
            const float4* xr = reinterpret_cast<const float4*>(&xa[m * HIDDEN + lane * 8]);
            float4 x1 = xr[0], x2 = xr[1];
            float par = x1.x * w1.x + x1.y * w1.y + x1.z * w1.z + x1.w * w1.w
                      + x2.x * w2.x + x2.y * w2.y + x2.z * w2.z + x2.w * w2.w;
            #pragma unroll
            for (int off = 16; off > 0; off >>= 1)
                par += __shfl_xor_sync(0xffffffff, par, off);
            if (lane == 0) out[base + m] = par + bfv;
        }
    }
}

extern "C" void kernel_launch(void* const* d_in, const int* in_sizes, int n_in,
                              void* d_out, int out_size)
{
    const float* coords = (const float*)d_in[0];
    const float* ow1    = (const float*)d_in[1];
    const float* ob1    = (const float*)d_in[2];
    const float* ow2    = (const float*)d_in[3];
    const float* ob2    = (const float*)d_in[4];
    const float* w0     = (const float*)d_in[5];
    const float* b0     = (const float*)d_in[6];
    const float* wh     = (const float*)d_in[7];
    const float* bh     = (const float*)d_in[8];
    const float* wf     = (const float*)d_in[9];
    const float* bf     = (const float*)d_in[10];
    float* out = (float*)d_out;

    int n = in_sizes[0] / 4;
    int grid = n / MTILE;
    size_t smem_bytes = (size_t)SMEM_FLOATS * sizeof(float);

    cudaFuncSetAttribute(siren_fused_kernel,
                         cudaFuncAttributeMaxDynamicSharedMemorySize,
                         (int)smem_bytes);
    siren_fused_kernel<<<grid, THREADS, smem_bytes>>>(
        coords, ow1, ob1, ow2, ob2, w0, b0, wh, bh, wf, bf, out);
}

// round 7
// speedup vs baseline: 2.4614x; 2.4614x over previous
#include <cuda_runtime.h>
#include <cuda_bf16.h>
#include <cstdint>

#define HIDDEN   256
#define NHL      4
#define MTILE    64          // points per CTA
#define THREADS  256
#define NCHUNK   16          // 4 layers * 4 k-chunks of 64
#define CHUNK_BYTES 32768    // [n=256][k=64] bf16 (hi or lo)

// pre-split, pre-transposed (W^T [n][k]), pre-swizzled weight images
__device__ __align__(16) __nv_bfloat16 g_bhi[NHL * HIDDEN * HIDDEN];
__device__ __align__(16) __nv_bfloat16 g_blo[NHL * HIDDEN * HIDDEN];

// ---- smem layout (bytes) ----
#define SM_AHI  0            // A hi  [64][256] bf16, 512B rows, swizzled
#define SM_ALO  32768        // A lo
#define SM_B    65536        // 2 bufs x (hi 32KB + lo 32KB) = 131072
#define SM_BHS  196608       // bh staged fp32 [4][256]
#define SM_WFS  200704       // wf fp32 [256]
#define SM_W0S  201728       // w0 fp32 [4][256]
#define SM_B0S  205824       // b0 fp32 [256]
#define SM_CS   206848       // coords [64][4]
#define SM_OMG  207872       // omega [64]
#define SM_PS   208128       // head partials [64][4]
#define SM_MBAR 209152       // 2 x 8B mbarriers
#define SM_TOTAL 209216

// ---- packed fp32x2 helpers ----
__device__ __forceinline__ uint64_t fma2v(uint64_t a, uint64_t b, uint64_t c) {
    uint64_t d; asm("fma.rn.f32x2 %0, %1, %2, %3;" : "=l"(d) : "l"(a), "l"(b), "l"(c)); return d;
}
__device__ __forceinline__ uint64_t mul2(uint64_t a, uint64_t b) {
    uint64_t d; asm("mul.rn.f32x2 %0, %1, %2;" : "=l"(d) : "l"(a), "l"(b)); return d;
}
__device__ __forceinline__ uint64_t add2(uint64_t a, uint64_t b) {
    uint64_t d; asm("add.rn.f32x2 %0, %1, %2;" : "=l"(d) : "l"(a), "l"(b)); return d;
}
__device__ __forceinline__ uint64_t dup2(float x) {
    uint64_t d; asm("mov.b64 %0, {%1, %1};" : "=l"(d) : "f"(x)); return d;
}
__device__ __forceinline__ uint64_t pack2(float lo, float hi) {
    uint64_t d; asm("mov.b64 %0, {%1, %2};" : "=l"(d) : "f"(lo), "f"(hi)); return d;
}
__device__ __forceinline__ void unpack2(float& lo, float& hi, uint64_t v) {
    asm("mov.b64 {%0, %1}, %2;" : "=f"(lo), "=f"(hi) : "l"(v));
}
__device__ __forceinline__ uint64_t c2(float x) {
    uint64_t d; asm("mov.b64 %0, {%1, %1};" : "=l"(d) : "f"(x)); return d;
}
// packed sine: magic range reduction to [-pi,pi] + degree-15 odd poly
__device__ __forceinline__ uint64_t sin2(uint64_t x) {
    uint64_t n = add2(fma2v(x, c2(0.15915494309189535f), c2(12582912.0f)),
                      c2(-12582912.0f));
    uint64_t r = fma2v(n, c2(-6.2831854820251465f), x);
    r = fma2v(n, c2(1.7484555e-7f), r);
    uint64_t r2 = mul2(r, r);
    uint64_t p = c2(-7.6471637e-13f);
    p = fma2v(p, r2, c2(1.6059044e-10f));
    p = fma2v(p, r2, c2(-2.5052108e-8f));
    p = fma2v(p, r2, c2(2.7557319e-6f));
    p = fma2v(p, r2, c2(-1.9841270e-4f));
    p = fma2v(p, r2, c2(8.3333333e-3f));
    p = fma2v(p, r2, c2(-1.6666667e-1f));
    p = fma2v(p, r2, c2(1.0f));
    return mul2(p, r);
}
// pack two fp32 -> bf16x2 (lo value in lower half)
__device__ __forceinline__ uint32_t cvt_bf16x2(float lo, float hi) {
    uint32_t r; asm("cvt.rn.bf16x2.f32 %0, %1, %2;" : "=r"(r) : "f"(hi), "f"(lo)); return r;
}

// ---- smem access (32-bit addresses) ----
__device__ __forceinline__ uint32_t lds32(uint32_t a) {
    uint32_t v; asm volatile("ld.shared.b32 %0, [%1];" : "=r"(v) : "r"(a)); return v;
}
__device__ __forceinline__ void sts32(uint32_t a, uint32_t v) {
    asm volatile("st.shared.b32 [%0], %1;" :: "r"(a), "r"(v) : "memory");
}

// ---- mbarrier / bulk copy ----
__device__ __forceinline__ void mbar_init(uint32_t mb, uint32_t cnt) {
    asm volatile("mbarrier.init.shared.b64 [%0], %1;" :: "r"(mb), "r"(cnt) : "memory");
}
__device__ __forceinline__ void mbar_expect_tx(uint32_t mb, uint32_t bytes) {
    asm volatile("mbarrier.arrive.expect_tx.shared.b64 _, [%0], %1;"
                 :: "r"(mb), "r"(bytes) : "memory");
}
__device__ __forceinline__ void mbar_wait(uint32_t mb, uint32_t parity) {
    asm volatile(
        "{\n\t.reg .pred P1;\n\t"
        "WL_%=:\n\t"
        "mbarrier.try_wait.parity.acquire.cta.shared::cta.b64 P1, [%0], %1, 0x989680;\n\t"
        "@P1 bra.uni WD_%=;\n\t"
        "bra.uni WL_%=;\n\t"
        "WD_%=:\n\t}"
        :: "r"(mb), "r"(parity) : "memory");
}
__device__ __forceinline__ void bulk_copy(uint32_t sdst, const void* gsrc,
                                          uint32_t bytes, uint32_t mb) {
    asm volatile(
        "cp.async.bulk.shared::cta.global.mbarrier::complete_tx::bytes [%0], [%1], %2, [%3];"
        :: "r"(sdst), "l"(gsrc), "r"(bytes), "r"(mb) : "memory");
}

// mma.sync m16n8k16 bf16 -> fp32
#define MMA(c, a, b) \
    asm volatile("mma.sync.aligned.m16n8k16.row.col.f32.bf16.bf16.f32 " \
        "{%0,%1,%2,%3}, {%4,%5,%6,%7}, {%8,%9}, {%0,%1,%2,%3};" \
        : "+f"((c)[0]), "+f"((c)[1]), "+f"((c)[2]), "+f"((c)[3]) \
        : "r"((a)[0]), "r"((a)[1]), "r"((a)[2]), "r"((a)[3]), \
          "r"((b)[0]), "r"((b)[1]))

// ---- prologue: split W into bf16 hi/lo, transpose to [n][k], chunk + swizzle ----
__global__ void convert_wh_kernel(const float* __restrict__ wh) {
    int idx = blockIdx.x * blockDim.x + threadIdx.x;
    if (idx >= NHL * HIDDEN * HIDDEN) return;
    int l = idx >> 16, r = idx & 65535, k = r >> 8, n = r & 255;
    float w = wh[idx];
    __nv_bfloat16 h  = __float2bfloat16(w);
    __nv_bfloat16 lo = __float2bfloat16(w - __bfloat162float(h));
    int chunk = l * 4 + (k >> 6);
    int off = chunk * CHUNK_BYTES + n * 128 + (((k & 63) * 2) ^ ((n & 7) << 4));
    *(__nv_bfloat16*)((char*)g_bhi + off) = h;
    *(__nv_bfloat16*)((char*)g_blo + off) = lo;
}

__device__ __forceinline__ void copy_chunk(int q, uint32_t sbase, uint32_t mbb) {
    uint32_t dst = sbase + SM_B + (uint32_t)(q & 1) * 65536;
    uint32_t mb = mbb + (uint32_t)(q & 1) * 8;
    mbar_expect_tx(mb, 2 * CHUNK_BYTES);
    bulk_copy(dst, (const char*)g_bhi + (size_t)q * CHUNK_BYTES, CHUNK_BYTES, mb);
    bulk_copy(dst + CHUNK_BYTES, (const char*)g_blo + (size_t)q * CHUNK_BYTES, CHUNK_BYTES, mb);
}

__global__ void __launch_bounds__(THREADS, 1)
siren_mma_kernel(const float* __restrict__ coords,
                 const float* __restrict__ ow1, const float* __restrict__ ob1,
                 const float* __restrict__ ow2, const float* __restrict__ ob2,
                 const float* __restrict__ w0,  const float* __restrict__ b0,
                 const float* __restrict__ bh,  const float* __restrict__ wf,
                 const float* __restrict__ bf,  float* __restrict__ out)
{
    extern __shared__ __align__(16) char smem[];
    float* bhs = (float*)(smem + SM_BHS);
    float* wfs = (float*)(smem + SM_WFS);
    float* w0s = (float*)(smem + SM_W0S);
    float* b0s = (float*)(smem + SM_B0S);
    float* cs  = (float*)(smem + SM_CS);
    float* omg = (float*)(smem + SM_OMG);
    float* ps  = (float*)(smem + SM_PS);

    const int tid  = threadIdx.x;
    const int wid  = tid >> 5;
    const int lane = tid & 31;
    const int gid  = lane >> 2;     // 0..7
    const int qd   = lane & 3;      // 0..3
    const int mw   = wid & 1;       // m strip (32 rows)
    const int nw   = wid >> 1;      // n strip (64 cols)
    const long base = (long)blockIdx.x * MTILE;

    const uint32_t sbase = (uint32_t)__cvta_generic_to_shared(smem);
    const uint32_t mbb   = sbase + SM_MBAR;
    const uint32_t swz   = (uint32_t)gid << 4;

    if (tid == 0) {
        mbar_init(mbb, 1);
        mbar_init(mbb + 8, 1);
        asm volatile("fence.proxy.async.shared::cta;" ::: "memory");
    }
    __syncthreads();
    if (tid == 0) copy_chunk(0, sbase, mbb);

    // stage small tensors
    cs[tid]  = coords[base * 4 + tid];
    wfs[tid] = wf[tid];
    b0s[tid] = b0[tid];
    #pragma unroll
    for (int r = 0; r < 4; r++) {
        w0s[tid + 256 * r] = w0[tid + 256 * r];
        bhs[tid + 256 * r] = bh[tid + 256 * r];
    }
    __syncthreads();

    // ---- omega predictor (threads 0..63) ----
    if (tid < MTILE) {
        float p0 = cs[tid * 4 + 0], p1 = cs[tid * 4 + 1];
        float p2 = cs[tid * 4 + 2], p3 = cs[tid * 4 + 3];
        float s = __ldg(ob2);
        #pragma unroll 4
        for (int j = 0; j < 64; j++) {
            float h = __ldg(&ow1[j]) * p0;
            h = fmaf(__ldg(&ow1[64  + j]), p1, h);
            h = fmaf(__ldg(&ow1[128 + j]), p2, h);
            h = fmaf(__ldg(&ow1[192 + j]), p3, h);
            h += __ldg(&ob1[j]);
            h = fmaxf(h, 0.0f);
            s = fmaf(h, __ldg(&ow2[j]), s);
        }
        float sig = 1.0f / (1.0f + __expf(-s));
        omg[tid] = 10.0f + 90.0f * sig;
    }
    __syncthreads();

    // ---- layer 0: A = sin(omega*(coords@w0+b0)) -> smem bf16 hi/lo (swizzled) ----
    {
        const int m0 = wid * 8;          // warp owns rows m0..m0+7
        const int nt = lane;             // col group: cA = nt*4, cB = 128+nt*4
        const int cA = nt * 4, cB = 128 + nt * 4;
        float accA[8][4], accB[8][4];
        #pragma unroll
        for (int i = 0; i < 8; i++)
            #pragma unroll
            for (int j = 0; j < 4; j++) { accA[i][j] = 0.0f; accB[i][j] = 0.0f; }
        #pragma unroll
        for (int k = 0; k < 4; k++) {
            float4 bA = *(const float4*)(w0s + k * HIDDEN + cA);
            float4 bB = *(const float4*)(w0s + k * HIDDEN + cB);
            #pragma unroll
            for (int i = 0; i < 8; i++) {
                float a = cs[(m0 + i) * 4 + k];
                accA[i][0] = fmaf(a, bA.x, accA[i][0]);
                accA[i][1] = fmaf(a, bA.y, accA[i][1]);
                accA[i][2] = fmaf(a, bA.z, accA[i][2]);
                accA[i][3] = fmaf(a, bA.w, accA[i][3]);
                accB[i][0] = fmaf(a, bB.x, accB[i][0]);
                accB[i][1] = fmaf(a, bB.y, accB[i][1]);
                accB[i][2] = fmaf(a, bB.z, accB[i][2]);
                accB[i][3] = fmaf(a, bB.w, accB[i][3]);
            }
        }
        uint64_t biA0 = *(const uint64_t*)(b0s + cA);
        uint64_t biA1 = *(const uint64_t*)(b0s + cA + 2);
        uint64_t biB0 = *(const uint64_t*)(b0s + cB);
        uint64_t biB1 = *(const uint64_t*)(b0s + cB + 2);
        #pragma unroll
        for (int i = 0; i < 8; i++) {
            int m = m0 + i;
            uint32_t swi = (uint32_t)(m & 7) << 4;
            uint32_t rowHi = sbase + SM_AHI + (uint32_t)m * 512;
            uint64_t om2 = dup2(omg[m]);
            uint64_t sv[4];
            sv[0] = sin2(mul2(om2, add2(pack2(accA[i][0], accA[i][1]), biA0)));
            sv[1] = sin2(mul2(om2, add2(pack2(accA[i][2], accA[i][3]), biA1)));
            sv[2] = sin2(mul2(om2, add2(pack2(accB[i][0], accB[i][1]), biB0)));
            sv[3] = sin2(mul2(om2, add2(pack2(accB[i][2], accB[i][3]), biB1)));
            uint32_t boff[4] = { (uint32_t)(cA*2) ^ swi, (uint32_t)(cA*2+4) ^ swi,
                                 (uint32_t)(cB*2) ^ swi, (uint32_t)(cB*2+4) ^ swi };
            #pragma unroll
            for (int j = 0; j < 4; j++) {
                float s0, s1; unpack2(s0, s1, sv[j]);
                uint32_t h = cvt_bf16x2(s0, s1);
                uint64_t hf = pack2(__uint_as_float(h << 16),
                                    __uint_as_float(h & 0xffff0000u));
                uint64_t rr = fma2v(hf, c2(-1.0f), sv[j]);
                float r0, r1; unpack2(r0, r1, rr);
                uint32_t lo = cvt_bf16x2(r0, r1);
                sts32(rowHi + boff[j], h);
                sts32(rowHi + 32768 + boff[j], lo);
            }
        }
    }

    // ---- 4 hidden layers via mma.sync bf16 split-3 ----
    #pragma unroll 1
    for (int l = 0; l < NHL; l++) {
        __syncthreads();   // new A visible to all warps

        float c[2][8][4];
        #pragma unroll
        for (int mt = 0; mt < 2; mt++)
            #pragma unroll
            for (int nt = 0; nt < 8; nt++)
                #pragma unroll
                for (int j = 0; j < 4; j++) c[mt][nt][j] = 0.0f;

        #pragma unroll 1
        for (int ch = 0; ch < 4; ch++) {
            int q = l * 4 + ch;
            if (tid == 0 && q + 1 < NCHUNK) copy_chunk(q + 1, sbase, mbb);
            mbar_wait(mbb + (q & 1) * 8, (q >> 1) & 1);

            uint32_t bhiB = sbase + SM_B + (uint32_t)(q & 1) * 65536;
            uint32_t bloB = bhiB + CHUNK_BYTES;

            #pragma unroll
            for (int ks = 0; ks < 4; ks++) {
                int kg = ch * 64 + ks * 16;
                uint32_t kA0 = (uint32_t)((kg + qd * 2) * 2) ^ swz;
                uint32_t kA1 = (uint32_t)((kg + qd * 2 + 8) * 2) ^ swz;
                uint32_t ah[2][4], al[2][4];
                #pragma unroll
                for (int mt = 0; mt < 2; mt++) {
                    uint32_t r0 = sbase + SM_AHI + (uint32_t)(mw*32 + mt*16 + gid) * 512;
                    ah[mt][0] = lds32(r0 + kA0);
                    ah[mt][1] = lds32(r0 + 4096 + kA0);
                    ah[mt][2] = lds32(r0 + kA1);
                    ah[mt][3] = lds32(r0 + 4096 + kA1);
                    uint32_t r1 = r0 + 32768;
                    al[mt][0] = lds32(r1 + kA0);
                    al[mt][1] = lds32(r1 + 4096 + kA0);
                    al[mt][2] = lds32(r1 + kA1);
                    al[mt][3] = lds32(r1 + 4096 + kA1);
                }
                uint32_t kB0 = (uint32_t)((ks*16 + qd*2) * 2) ^ swz;
                uint32_t kB1 = (uint32_t)((ks*16 + qd*2 + 8) * 2) ^ swz;
                uint32_t bhf[8][2], blf[8][2];
                #pragma unroll
                for (int nt = 0; nt < 8; nt++) {
                    uint32_t rb = bhiB + (uint32_t)(nw*64 + nt*8 + gid) * 128;
                    bhf[nt][0] = lds32(rb + kB0);
                    bhf[nt][1] = lds32(rb + kB1);
                    uint32_t rl = rb + CHUNK_BYTES;
                    blf[nt][0] = lds32(rl + kB0);
                    blf[nt][1] = lds32(rl + kB1);
                }
                #pragma unroll
                for (int mt = 0; mt < 2; mt++)
                    #pragma unroll
                    for (int nt = 0; nt < 8; nt++) MMA(c[mt][nt], ah[mt], bhf[nt]);
                #pragma unroll
                for (int mt = 0; mt < 2; mt++)
                    #pragma unroll
                    for (int nt = 0; nt < 8; nt++) MMA(c[mt][nt], al[mt], bhf[nt]);
                #pragma unroll
                for (int mt = 0; mt < 2; mt++)
                    #pragma unroll
                    for (int nt = 0; nt < 8; nt++) MMA(c[mt][nt], ah[mt], blf[nt]);
            }
            __syncthreads();   // buffer q&1 consumed before refill next chunk
        }

        // ---- epilogue ----
        const float* bhl = bhs + l * 256;
        if (l < NHL - 1) {
            #pragma unroll
            for (int mt = 0; mt < 2; mt++) {
                int m = mw * 32 + mt * 16 + gid;
                uint64_t om0 = dup2(omg[m]);
                uint64_t om8 = dup2(omg[m + 8]);
                uint32_t row0 = sbase + SM_AHI + (uint32_t)m * 512;
                uint32_t row8 = row0 + 4096;
                #pragma unroll
                for (int nt = 0; nt < 8; nt++) {
                    int n0 = nw * 64 + nt * 8 + qd * 2;
                    uint64_t bias = *(const uint64_t*)(bhl + n0);
                    uint32_t boff = (uint32_t)(n0 * 2) ^ swz;
                    uint64_t s0 = sin2(mul2(om0, add2(pack2(c[mt][nt][0], c[mt][nt][1]), bias)));
                    uint64_t s8 = sin2(mul2(om8, add2(pack2(c[mt][nt][2], c[mt][nt][3]), bias)));
                    float x0, x1; unpack2(x0, x1, s0);
                    uint32_t h0 = cvt_bf16x2(x0, x1);
                    uint64_t hf0 = pack2(__uint_as_float(h0 << 16),
                                         __uint_as_float(h0 & 0xffff0000u));
                    uint64_t rr0 = fma2v(hf0, c2(-1.0f), s0);
                    unpack2(x0, x1, rr0);
                    uint32_t l0 = cvt_bf16x2(x0, x1);
                    sts32(row0 + boff, h0);
                    sts32(row0 + 32768 + boff, l0);
                    float y0, y1; unpack2(y0, y1, s8);
                    uint32_t h8 = cvt_bf16x2(y0, y1);
                    uint64_t hf8 = pack2(__uint_as_float(h8 << 16),
                                         __uint_as_float(h8 & 0xffff0000u));
                    uint64_t rr8 = fma2v(hf8, c2(-1.0f), s8);
                    unpack2(y0, y1, rr8);
                    uint32_t l8 = cvt_bf16x2(y0, y1);
                    sts32(row8 + boff, h8);
                    sts32(row8 + 32768 + boff, l8);
                }
            }
        } else {
            // fused head: sin + dot with wf, quad-shuffle reduce
            #pragma unroll
            for (int mt = 0; mt < 2; mt++) {
                int m = mw * 32 + mt * 16 + gid;
                uint64_t om0 = dup2(omg[m]);
                uint64_t om8 = dup2(omg[m + 8]);
                uint64_t acc0 = 0ull, acc8 = 0ull;
                #pragma unroll
                for (int nt = 0; nt < 8; nt++) {
                    int n0 = nw * 64 + nt * 8 + qd * 2;
                    uint64_t bias = *(const uint64_t*)(bhl + n0);
                    uint64_t wfp  = *(const uint64_t*)(wfs + n0);
                    uint64_t s0 = sin2(mul2(om0, add2(pack2(c[mt][nt][0], c[mt][nt][1]), bias)));
                    uint64_t s8 = sin2(mul2(om8, add2(pack2(c[mt][nt][2], c[mt][nt][3]), bias)));
                    acc0 = fma2v(s0, wfp, acc0);
                    acc8 = fma2v(s8, wfp, acc8);
                }
                float a0, a1; unpack2(a0, a1, acc0); float p0 = a0 + a1;
                float b0v, b1v; unpack2(b0v, b1v, acc8); float p8 = b0v + b1v;
                p0 += __shfl_xor_sync(0xffffffffu, p0, 1);
                p0 += __shfl_xor_sync(0xffffffffu, p0, 2);
                p8 += __shfl_xor_sync(0xffffffffu, p8, 1);
                p8 += __shfl_xor_sync(0xffffffffu, p8, 2);
                if (qd == 0) {
                    ps[m * 4 + nw] = p0;
                    ps[(m + 8) * 4 + nw] = p8;
                }
            }
        }
    }

    __syncthreads();
    if (tid < MTILE)
        out[base + tid] = ps[tid * 4] + ps[tid * 4 + 1] + ps[tid * 4 + 2]
                        + ps[tid * 4 + 3] + __ldg(bf);
}

extern "C" void kernel_launch(void* const* d_in, const int* in_sizes, int n_in,
                              void* d_out, int out_size)
{
    const float* coords = (const float*)d_in[0];
    const float* ow1    = (const float*)d_in[1];
    const float* ob1    = (const float*)d_in[2];
    const float* ow2    = (const float*)d_in[3];
    const float* ob2    = (const float*)d_in[4];
    const float* w0     = (const float*)d_in[5];
    const float* b0     = (const float*)d_in[6];
    const float* wh     = (const float*)d_in[7];
    const float* bh     = (const float*)d_in[8];
    const float* wf     = (const float*)d_in[9];
    const float* bf     = (const float*)d_in[10];
    float* out = (float*)d_out;

    int n = in_sizes[0] / 4;

    convert_wh_kernel<<<(NHL * HIDDEN * HIDDEN + 255) / 256, 256>>>(wh);

    cudaFuncSetAttribute(siren_mma_kernel,
                         cudaFuncAttributeMaxDynamicSharedMemorySize, SM_TOTAL);
    siren_mma_kernel<<<n / MTILE, THREADS, SM_TOTAL>>>(
        coords, ow1, ob1, ow2, ob2, w0, b0, bh, wf, bf, out);
}

// round 8
// speedup vs baseline: 2.6129x; 1.0615x over previous
#include <cuda_runtime.h>
#include <cuda_bf16.h>
#include <cstdint>

#define HIDDEN   256
#define NHL      4
#define MTILE    64          // points per CTA
#define THREADS  256
#define NCHUNK   64          // 4 layers * 16 k-chunks of 16
#define CHUNK_BYTES 8192     // [n=256][k=16] bf16 (hi or lo)

// pre-split, pre-transposed (W^T [n][k]), pre-swizzled weight images
__device__ __align__(16) __nv_bfloat16 g_bhi[NHL * HIDDEN * HIDDEN];
__device__ __align__(16) __nv_bfloat16 g_blo[NHL * HIDDEN * HIDDEN];

// ---- smem layout (bytes) ---- total ~108.3 KB -> 2 CTAs/SM
#define SM_AHI  0            // A hi  [64][256] bf16, 512B rows, swizzled
#define SM_ALO  32768        // A lo
#define SM_B    65536        // 2 bufs x (hi 8KB + lo 8KB) = 32768
#define SM_BHS  98304        // bh fp32 [4][256]
#define SM_WFS  102400       // wf fp32 [256]
#define SM_W0S  103424       // w0 fp32 [4][256]
#define SM_B0S  107520       // b0 fp32 [256]
#define SM_CS   108544       // coords [64][4]
#define SM_OMG  109568       // omega [64]
#define SM_PS   109824       // head partials [64][4]
#define SM_MBAR 110848       // 2 x 8B mbarriers
#define SM_TOTAL 110912

// ---- packed fp32x2 helpers ----
__device__ __forceinline__ uint64_t fma2v(uint64_t a, uint64_t b, uint64_t c) {
    uint64_t d; asm("fma.rn.f32x2 %0, %1, %2, %3;" : "=l"(d) : "l"(a), "l"(b), "l"(c)); return d;
}
__device__ __forceinline__ uint64_t mul2(uint64_t a, uint64_t b) {
    uint64_t d; asm("mul.rn.f32x2 %0, %1, %2;" : "=l"(d) : "l"(a), "l"(b)); return d;
}
__device__ __forceinline__ uint64_t add2(uint64_t a, uint64_t b) {
    uint64_t d; asm("add.rn.f32x2 %0, %1, %2;" : "=l"(d) : "l"(a), "l"(b)); return d;
}
__device__ __forceinline__ uint64_t dup2(float x) {
    uint64_t d; asm("mov.b64 %0, {%1, %1};" : "=l"(d) : "f"(x)); return d;
}
__device__ __forceinline__ uint64_t pack2(float lo, float hi) {
    uint64_t d; asm("mov.b64 %0, {%1, %2};" : "=l"(d) : "f"(lo), "f"(hi)); return d;
}
__device__ __forceinline__ void unpack2(float& lo, float& hi, uint64_t v) {
    asm("mov.b64 {%0, %1}, %2;" : "=f"(lo), "=f"(hi) : "l"(v));
}
__device__ __forceinline__ uint64_t c2(float x) {
    uint64_t d; asm("mov.b64 %0, {%1, %1};" : "=l"(d) : "f"(x)); return d;
}
// packed sine: magic range reduction to [-pi,pi] + degree-15 odd poly
__device__ __forceinline__ uint64_t sin2(uint64_t x) {
    uint64_t n = add2(fma2v(x, c2(0.15915494309189535f), c2(12582912.0f)),
                      c2(-12582912.0f));
    uint64_t r = fma2v(n, c2(-6.2831854820251465f), x);
    r = fma2v(n, c2(1.7484555e-7f), r);
    uint64_t r2 = mul2(r, r);
    uint64_t p = c2(-7.6471637e-13f);
    p = fma2v(p, r2, c2(1.6059044e-10f));
    p = fma2v(p, r2, c2(-2.5052108e-8f));
    p = fma2v(p, r2, c2(2.7557319e-6f));
    p = fma2v(p, r2, c2(-1.9841270e-4f));
    p = fma2v(p, r2, c2(8.3333333e-3f));
    p = fma2v(p, r2, c2(-1.6666667e-1f));
    p = fma2v(p, r2, c2(1.0f));
    return mul2(p, r);
}
__device__ __forceinline__ uint32_t cvt_bf16x2(float lo, float hi) {
    uint32_t r; asm("cvt.rn.bf16x2.f32 %0, %1, %2;" : "=r"(r) : "f"(hi), "f"(lo)); return r;
}

__device__ __forceinline__ uint32_t lds32(uint32_t a) {
    uint32_t v; asm volatile("ld.shared.b32 %0, [%1];" : "=r"(v) : "r"(a)); return v;
}
__device__ __forceinline__ void sts32(uint32_t a, uint32_t v) {
    asm volatile("st.shared.b32 [%0], %1;" :: "r"(a), "r"(v) : "memory");
}

// ---- mbarrier / bulk copy ----
__device__ __forceinline__ void mbar_init(uint32_t mb, uint32_t cnt) {
    asm volatile("mbarrier.init.shared.b64 [%0], %1;" :: "r"(mb), "r"(cnt) : "memory");
}
__device__ __forceinline__ void mbar_expect_tx(uint32_t mb, uint32_t bytes) {
    asm volatile("mbarrier.arrive.expect_tx.shared.b64 _, [%0], %1;"
                 :: "r"(mb), "r"(bytes) : "memory");
}
__device__ __forceinline__ void mbar_wait(uint32_t mb, uint32_t parity) {
    asm volatile(
        "{\n\t.reg .pred P1;\n\t"
        "WL_%=:\n\t"
        "mbarrier.try_wait.parity.acquire.cta.shared::cta.b64 P1, [%0], %1, 0x989680;\n\t"
        "@P1 bra.uni WD_%=;\n\t"
        "bra.uni WL_%=;\n\t"
        "WD_%=:\n\t}"
        :: "r"(mb), "r"(parity) : "memory");
}
__device__ __forceinline__ void bulk_copy(uint32_t sdst, const void* gsrc,
                                          uint32_t bytes, uint32_t mb) {
    asm volatile(
        "cp.async.bulk.shared::cta.global.mbarrier::complete_tx::bytes [%0], [%1], %2, [%3];"
        :: "r"(sdst), "l"(gsrc), "r"(bytes), "r"(mb) : "memory");
}

// mma.sync m16n8k16 bf16 -> fp32
#define MMA(c, a, b) \
    asm volatile("mma.sync.aligned.m16n8k16.row.col.f32.bf16.bf16.f32 " \
        "{%0,%1,%2,%3}, {%4,%5,%6,%7}, {%8,%9}, {%0,%1,%2,%3};" \
        : "+f"((c)[0]), "+f"((c)[1]), "+f"((c)[2]), "+f"((c)[3]) \
        : "r"((a)[0]), "r"((a)[1]), "r"((a)[2]), "r"((a)[3]), \
          "r"((b)[0]), "r"((b)[1]))

// ---- prologue: split W into bf16 hi/lo, transpose to [n][k], chunk (k=16) + swizzle ----
__global__ void convert_wh_kernel(const float* __restrict__ wh) {
    int idx = blockIdx.x * blockDim.x + threadIdx.x;
    if (idx >= NHL * HIDDEN * HIDDEN) return;
    int l = idx >> 16, r = idx & 65535, k = r >> 8, n = r & 255;
    float w = wh[idx];
    __nv_bfloat16 h  = __float2bfloat16(w);
    __nv_bfloat16 lo = __float2bfloat16(w - __bfloat162float(h));
    int chunk = l * 16 + (k >> 4);
    int off = chunk * CHUNK_BYTES + n * 32 + ((((k & 15) * 2)) ^ ((n & 7) << 2));
    *(__nv_bfloat16*)((char*)g_bhi + off) = h;
    *(__nv_bfloat16*)((char*)g_blo + off) = lo;
}

__device__ __forceinline__ void copy_chunk(int q, uint32_t sbase, uint32_t mbb) {
    uint32_t dst = sbase + SM_B + (uint32_t)(q & 1) * (2 * CHUNK_BYTES);
    uint32_t mb = mbb + (uint32_t)(q & 1) * 8;
    mbar_expect_tx(mb, 2 * CHUNK_BYTES);
    bulk_copy(dst, (const char*)g_bhi + (size_t)q * CHUNK_BYTES, CHUNK_BYTES, mb);
    bulk_copy(dst + CHUNK_BYTES, (const char*)g_blo + (size_t)q * CHUNK_BYTES, CHUNK_BYTES, mb);
}

__global__ void __launch_bounds__(THREADS, 2)
siren_mma_kernel(const float* __restrict__ coords,
                 const float* __restrict__ ow1, const float* __restrict__ ob1,
                 const float* __restrict__ ow2, const float* __restrict__ ob2,
                 const float* __restrict__ w0,  const float* __restrict__ b0,
                 const float* __restrict__ bh,  const float* __restrict__ wf,
                 const float* __restrict__ bf,  float* __restrict__ out)
{
    extern __shared__ __align__(16) char smem[];
    float* bhs = (float*)(smem + SM_BHS);
    float* wfs = (float*)(smem + SM_WFS);
    float* w0s = (float*)(smem + SM_W0S);
    float* b0s = (float*)(smem + SM_B0S);
    float* cs  = (float*)(smem + SM_CS);
    float* omg = (float*)(smem + SM_OMG);
    float* ps  = (float*)(smem + SM_PS);

    const int tid  = threadIdx.x;
    const int wid  = tid >> 5;
    const int lane = tid & 31;
    const int gid  = lane >> 2;     // 0..7
    const int qd   = lane & 3;      // 0..3
    const int mw   = wid & 1;       // m strip (32 rows)
    const int nw   = wid >> 1;      // n strip (64 cols)
    const long base = (long)blockIdx.x * MTILE;

    const uint32_t sbase = (uint32_t)__cvta_generic_to_shared(smem);
    const uint32_t mbb   = sbase + SM_MBAR;
    const uint32_t swzA  = (uint32_t)gid << 4;     // A row swizzle
    const uint32_t swzB  = (uint32_t)gid << 2;     // B row swizzle

    if (tid == 0) {
        mbar_init(mbb, 1);
        mbar_init(mbb + 8, 1);
        asm volatile("fence.proxy.async.shared::cta;" ::: "memory");
    }
    __syncthreads();
    if (tid == 0) copy_chunk(0, sbase, mbb);

    // stage small tensors
    cs[tid]  = coords[base * 4 + tid];
    wfs[tid] = wf[tid];
    b0s[tid] = b0[tid];
    #pragma unroll
    for (int r = 0; r < 4; r++) {
        w0s[tid + 256 * r] = w0[tid + 256 * r];
        bhs[tid + 256 * r] = bh[tid + 256 * r];
    }
    __syncthreads();

    // ---- omega predictor (threads 0..63) ----
    if (tid < MTILE) {
        float p0 = cs[tid * 4 + 0], p1 = cs[tid * 4 + 1];
        float p2 = cs[tid * 4 + 2], p3 = cs[tid * 4 + 3];
        float s = __ldg(ob2);
        #pragma unroll 4
        for (int j = 0; j < 64; j++) {
            float h = __ldg(&ow1[j]) * p0;
            h = fmaf(__ldg(&ow1[64  + j]), p1, h);
            h = fmaf(__ldg(&ow1[128 + j]), p2, h);
            h = fmaf(__ldg(&ow1[192 + j]), p3, h);
            h += __ldg(&ob1[j]);
            h = fmaxf(h, 0.0f);
            s = fmaf(h, __ldg(&ow2[j]), s);
        }
        float sig = 1.0f / (1.0f + __expf(-s));
        omg[tid] = 10.0f + 90.0f * sig;
    }
    __syncthreads();

    // ---- layer 0: A = sin(omega*(coords@w0+b0)) -> smem bf16 hi/lo (swizzled) ----
    {
        const int m0 = wid * 8;
        const int cA = lane * 4, cB = 128 + lane * 4;
        float accA[8][4], accB[8][4];
        #pragma unroll
        for (int i = 0; i < 8; i++)
            #pragma unroll
            for (int j = 0; j < 4; j++) { accA[i][j] = 0.0f; accB[i][j] = 0.0f; }
        #pragma unroll
        for (int k = 0; k < 4; k++) {
            float4 bA = *(const float4*)(w0s + k * HIDDEN + cA);
            float4 bB = *(const float4*)(w0s + k * HIDDEN + cB);
            #pragma unroll
            for (int i = 0; i < 8; i++) {
                float a = cs[(m0 + i) * 4 + k];
                accA[i][0] = fmaf(a, bA.x, accA[i][0]);
                accA[i][1] = fmaf(a, bA.y, accA[i][1]);
                accA[i][2] = fmaf(a, bA.z, accA[i][2]);
                accA[i][3] = fmaf(a, bA.w, accA[i][3]);
                accB[i][0] = fmaf(a, bB.x, accB[i][0]);
                accB[i][1] = fmaf(a, bB.y, accB[i][1]);
                accB[i][2] = fmaf(a, bB.z, accB[i][2]);
                accB[i][3] = fmaf(a, bB.w, accB[i][3]);
            }
        }
        uint64_t biA0 = *(const uint64_t*)(b0s + cA);
        uint64_t biA1 = *(const uint64_t*)(b0s + cA + 2);
        uint64_t biB0 = *(const uint64_t*)(b0s + cB);
        uint64_t biB1 = *(const uint64_t*)(b0s + cB + 2);
        #pragma unroll
        for (int i = 0; i < 8; i++) {
            int m = m0 + i;
            uint32_t swi = (uint32_t)(m & 7) << 4;
            uint32_t rowHi = sbase + SM_AHI + (uint32_t)m * 512;
            uint64_t om2 = dup2(omg[m]);
            uint64_t sv[4];
            sv[0] = sin2(mul2(om2, add2(pack2(accA[i][0], accA[i][1]), biA0)));
            sv[1] = sin2(mul2(om2, add2(pack2(accA[i][2], accA[i][3]), biA1)));
            sv[2] = sin2(mul2(om2, add2(pack2(accB[i][0], accB[i][1]), biB0)));
            sv[3] = sin2(mul2(om2, add2(pack2(accB[i][2], accB[i][3]), biB1)));
            uint32_t boff[4] = { (uint32_t)(cA*2) ^ swi, (uint32_t)(cA*2+4) ^ swi,
                                 (uint32_t)(cB*2) ^ swi, (uint32_t)(cB*2+4) ^ swi };
            #pragma unroll
            for (int j = 0; j < 4; j++) {
                float s0, s1; unpack2(s0, s1, sv[j]);
                uint32_t h = cvt_bf16x2(s0, s1);
                uint64_t hf = pack2(__uint_as_float(h << 16),
                                    __uint_as_float(h & 0xffff0000u));
                uint64_t rr = fma2v(hf, c2(-1.0f), sv[j]);
                float r0, r1; unpack2(r0, r1, rr);
                uint32_t lo = cvt_bf16x2(r0, r1);
                sts32(rowHi + boff[j], h);
                sts32(rowHi + 32768 + boff[j], lo);
            }
        }
    }

    // ---- 4 hidden layers via mma.sync bf16 split-3, k=16 chunks ----
    #pragma unroll 1
    for (int l = 0; l < NHL; l++) {
        __syncthreads();   // new A visible to all warps

        float c[2][8][4];
        #pragma unroll
        for (int mt = 0; mt < 2; mt++)
            #pragma unroll
            for (int nt = 0; nt < 8; nt++)
                #pragma unroll
                for (int j = 0; j < 4; j++) c[mt][nt][j] = 0.0f;

        #pragma unroll 1
        for (int ch = 0; ch < 16; ch++) {
            int q = l * 16 + ch;
            if (tid == 0 && q + 1 < NCHUNK) copy_chunk(q + 1, sbase, mbb);
            mbar_wait(mbb + (q & 1) * 8, (q >> 1) & 1);

            uint32_t bB = sbase + SM_B + (uint32_t)(q & 1) * (2 * CHUNK_BYTES);
            int kg = ch * 16;
            uint32_t kA0 = (uint32_t)((kg + qd * 2) * 2) ^ swzA;
            uint32_t kA1 = (uint32_t)((kg + qd * 2 + 8) * 2) ^ swzA;

            uint32_t ah[2][4], al[2][4];
            #pragma unroll
            for (int mt = 0; mt < 2; mt++) {
                uint32_t r0 = sbase + SM_AHI + (uint32_t)(mw*32 + mt*16 + gid) * 512;
                ah[mt][0] = lds32(r0 + kA0);
                ah[mt][1] = lds32(r0 + 4096 + kA0);
                ah[mt][2] = lds32(r0 + kA1);
                ah[mt][3] = lds32(r0 + 4096 + kA1);
                uint32_t r1 = r0 + 32768;
                al[mt][0] = lds32(r1 + kA0);
                al[mt][1] = lds32(r1 + 4096 + kA0);
                al[mt][2] = lds32(r1 + kA1);
                al[mt][3] = lds32(r1 + 4096 + kA1);
            }
            uint32_t kB0 = ((uint32_t)(qd * 4)) ^ swzB;
            uint32_t kB1 = ((uint32_t)(qd * 4 + 16)) ^ swzB;
            uint32_t bfr[8][2];
            #pragma unroll
            for (int nt = 0; nt < 8; nt++) {
                uint32_t rb = bB + (uint32_t)(nw*64 + nt*8 + gid) * 32;
                bfr[nt][0] = lds32(rb + kB0);
                bfr[nt][1] = lds32(rb + kB1);
            }
            #pragma unroll
            for (int mt = 0; mt < 2; mt++)
                #pragma unroll
                for (int nt = 0; nt < 8; nt++) MMA(c[mt][nt], ah[mt], bfr[nt]);
            #pragma unroll
            for (int mt = 0; mt < 2; mt++)
                #pragma unroll
                for (int nt = 0; nt < 8; nt++) MMA(c[mt][nt], al[mt], bfr[nt]);
            // reload bfr with lo-weights (reuse registers)
            #pragma unroll
            for (int nt = 0; nt < 8; nt++) {
                uint32_t rl = bB + CHUNK_BYTES + (uint32_t)(nw*64 + nt*8 + gid) * 32;
                bfr[nt][0] = lds32(rl + kB0);
                bfr[nt][1] = lds32(rl + kB1);
            }
            #pragma unroll
            for (int mt = 0; mt < 2; mt++)
                #pragma unroll
                for (int nt = 0; nt < 8; nt++) MMA(c[mt][nt], ah[mt], bfr[nt]);
            __syncthreads();   // buffer q&1 consumed before its refill
        }

        // ---- epilogue ----
        const float* bhl = bhs + l * 256;
        if (l < NHL - 1) {
            #pragma unroll
            for (int mt = 0; mt < 2; mt++) {
                int m = mw * 32 + mt * 16 + gid;
                uint64_t om0 = dup2(omg[m]);
                uint64_t om8 = dup2(omg[m + 8]);
                uint32_t row0 = sbase + SM_AHI + (uint32_t)m * 512;
                uint32_t row8 = row0 + 4096;
                #pragma unroll
                for (int nt = 0; nt < 8; nt++) {
                    int n0 = nw * 64 + nt * 8 + qd * 2;
                    uint64_t bias = *(const uint64_t*)(bhl + n0);
                    uint32_t boff = (uint32_t)(n0 * 2) ^ ((uint32_t)(m & 7) << 4);
                    uint32_t boff8 = (uint32_t)(n0 * 2) ^ ((uint32_t)((m + 8) & 7) << 4);
                    uint64_t s0 = sin2(mul2(om0, add2(pack2(c[mt][nt][0], c[mt][nt][1]), bias)));
                    uint64_t s8 = sin2(mul2(om8, add2(pack2(c[mt][nt][2], c[mt][nt][3]), bias)));
                    float x0, x1; unpack2(x0, x1, s0);
                    uint32_t h0 = cvt_bf16x2(x0, x1);
                    uint64_t hf0 = pack2(__uint_as_float(h0 << 16),
                                         __uint_as_float(h0 & 0xffff0000u));
                    uint64_t rr0 = fma2v(hf0, c2(-1.0f), s0);
                    unpack2(x0, x1, rr0);
                    uint32_t l0 = cvt_bf16x2(x0, x1);
                    sts32(row0 + boff, h0);
                    sts32(row0 + 32768 + boff, l0);
                    float y0, y1; unpack2(y0, y1, s8);
                    uint32_t h8 = cvt_bf16x2(y0, y1);
                    uint64_t hf8 = pack2(__uint_as_float(h8 << 16),
                                         __uint_as_float(h8 & 0xffff0000u));
                    uint64_t rr8 = fma2v(hf8, c2(-1.0f), s8);
                    unpack2(y0, y1, rr8);
                    uint32_t l8 = cvt_bf16x2(y0, y1);
                    sts32(row8 + boff8, h8);
                    sts32(row8 + 32768 + boff8, l8);
                }
            }
        } else {
            // fused head: sin + dot with wf, quad-shuffle reduce
            #pragma unroll
            for (int mt = 0; mt < 2; mt++) {
                int m = mw * 32 + mt * 16 + gid;
                uint64_t om0 = dup2(omg[m]);
                uint64_t om8 = dup2(omg[m + 8]);
                uint64_t acc0 = 0ull, acc8 = 0ull;
                #pragma unroll
                for (int nt = 0; nt < 8; nt++) {
                    int n0 = nw * 64 + nt * 8 + qd * 2;
                    uint64_t bias = *(const uint64_t*)(bhl + n0);
                    uint64_t wfp  = *(const uint64_t*)(wfs + n0);
                    uint64_t s0 = sin2(mul2(om0, add2(pack2(c[mt][nt][0], c[mt][nt][1]), bias)));
                    uint64_t s8 = sin2(mul2(om8, add2(pack2(c[mt][nt][2], c[mt][nt][3]), bias)));
                    acc0 = fma2v(s0, wfp, acc0);
                    acc8 = fma2v(s8, wfp, acc8);
                }
                float a0, a1; unpack2(a0, a1, acc0); float p0 = a0 + a1;
                float b0v, b1v; unpack2(b0v, b1v, acc8); float p8 = b0v + b1v;
                p0 += __shfl_xor_sync(0xffffffffu, p0, 1);
                p0 += __shfl_xor_sync(0xffffffffu, p0, 2);
                p8 += __shfl_xor_sync(0xffffffffu, p8, 1);
                p8 += __shfl_xor_sync(0xffffffffu, p8, 2);
                if (qd == 0) {
                    ps[m * 4 + nw] = p0;
                    ps[(m + 8) * 4 + nw] = p8;
                }
            }
        }
    }

    __syncthreads();
    if (tid < MTILE)
        out[base + tid] = ps[tid * 4] + ps[tid * 4 + 1] + ps[tid * 4 + 2]
                        + ps[tid * 4 + 3] + __ldg(bf);
}

extern "C" void kernel_launch(void* const* d_in, const int* in_sizes, int n_in,
                              void* d_out, int out_size)
{
    const float* coords = (const float*)d_in[0];
    const float* ow1    = (const float*)d_in[1];
    const float* ob1    = (const float*)d_in[2];
    const float* ow2    = (const float*)d_in[3];
    const float* ob2    = (const float*)d_in[4];
    const float* w0     = (const float*)d_in[5];
    const float* b0     = (const float*)d_in[6];
    const float* wh     = (const float*)d_in[7];
    const float* bh     = (const float*)d_in[8];
    const float* wf     = (const float*)d_in[9];
    const float* bf     = (const float*)d_in[10];
    float* out = (float*)d_out;

    int n = in_sizes[0] / 4;

    convert_wh_kernel<<<(NHL * HIDDEN * HIDDEN + 255) / 256, 256>>>(wh);

    cudaFuncSetAttribute(siren_mma_kernel,
                         cudaFuncAttributeMaxDynamicSharedMemorySize, SM_TOTAL);
    siren_mma_kernel<<<n / MTILE, THREADS, SM_TOTAL>>>(
        coords, ow1, ob1, ow2, ob2, w0, b0, bh, wf, bf, out);
}